// round 17
// baseline (speedup 1.0000x reference)
#include <cuda_runtime.h>
#include <math.h>
#include <stdint.h>

#define NN 1024
#define FD 32
#define ED 20
#define JT 32            // j per tile (per CTA, both i-rows)
#define NT (NN / JT)     // 32 tiles
#define NSTAGE 4

typedef unsigned long long ull;

// Precomputed per-j packs (verified R9/R12/R15):
//  g_lv[j*32+f] = (La*V0, La*V1, La*V2, Lb)
//  g_lc[j*32+f] = Lc
__device__ float4 g_lv[NN * 32];
__device__ float  g_lc[NN * 32];

// ---- f32x2 helpers (verified R8/R12/R15) ----
__device__ __forceinline__ ull ffma2(ull a, ull b, ull c) {
    ull d; asm("fma.rn.f32x2 %0, %1, %2, %3;" : "=l"(d) : "l"(a), "l"(b), "l"(c)); return d;
}
__device__ __forceinline__ ull pack2(float lo, float hi) {
    ull r; asm("mov.b64 %0, {%1, %2};" : "=l"(r) : "f"(lo), "f"(hi)); return r;
}
__device__ __forceinline__ float f2lo(ull p) { return __int_as_float((int)(unsigned)p); }
__device__ __forceinline__ float f2hi(ull p) { return __int_as_float((int)(p >> 32)); }

// ---- cp.async helpers ----
__device__ __forceinline__ void cp16(uint32_t dst, const void* src) {
    asm volatile("cp.async.ca.shared.global [%0], [%1], 16;" :: "r"(dst), "l"(src));
}
#define CP_COMMIT() asm volatile("cp.async.commit_group;" ::: "memory")
#define CP_WAIT2()  asm volatile("cp.async.wait_group 2;" ::: "memory")

// Per-tile staged buffer, float4 units (32 j, TWO i-rows):
// [0,160)    X0   (32 j x 20 floats, row i0)
// [160,320)  X1   (row i1)
// [320,344)  dir0 (32 j x 3 floats)
// [344,368)  dir1
// [368,376)  mask0 (32 floats)
// [376,384)  mask1
#define TB_F4 384

// ---------------------------------------------------------------------------
// Kernel 1: per-node msg_left MLP -> packed LV / Lc.  grid=NN, block=96.
// ---------------------------------------------------------------------------
__global__ void left_kernel(const float* __restrict__ scalar,
                            const float* __restrict__ vector,
                            const float* __restrict__ w1, const float* __restrict__ b1,
                            const float* __restrict__ w2, const float* __restrict__ b2) {
    int j = blockIdx.x;
    int t = threadIdx.x;
    __shared__ float ss[FD];
    __shared__ float sh[FD];
    __shared__ float sL[96];
    if (t < FD) ss[t] = scalar[j * FD + t];
    __syncthreads();
    if (t < FD) {
        float acc = b1[t];
#pragma unroll
        for (int k = 0; k < FD; k++) acc += ss[k] * w1[k * FD + t];
        sh[t] = acc / (1.0f + expf(-acc));   // silu
    }
    __syncthreads();
    float acc = b2[t];
#pragma unroll
    for (int k = 0; k < FD; k++) acc += sh[k] * w2[k * 96 + t];
    sL[t] = acc;
    __syncthreads();
    if (t < 32) {
        float La = sL[t], Lb = sL[32 + t], Lc = sL[64 + t];
        float v0 = vector[j * 96 + t];
        float v1 = vector[j * 96 + 32 + t];
        float v2 = vector[j * 96 + 64 + t];
        g_lv[j * 32 + t] = make_float4(La * v0, La * v1, La * v2, Lb);
        g_lc[j * 32 + t] = Lc;
    }
}

// ---------------------------------------------------------------------------
// Stage one 32-j tile for BOTH i-rows via cp.async. 384 float4, 256 threads.
// ---------------------------------------------------------------------------
__device__ __forceinline__ void stage_tile(
        float4* buf, int j0, int tid,
        const float* X0g, const float* X1g,
        const float* D0g, const float* D1g,
        const float* M0g, const float* M1g) {
    uint32_t dst = (uint32_t)__cvta_generic_to_shared(buf);
    {   // k = tid in [0,256)
        int k = tid;
        const float4* s;
        if (k < 160)      s = (const float4*)(X0g + j0 * ED) + k;
        else              s = (const float4*)(X1g + j0 * ED) + (k - 160);
        cp16(dst + (uint32_t)k * 16u, s);
    }
    {   // k in [256,384)
        int k = tid + 256;
        if (k < TB_F4) {
            const float4* s;
            if (k < 320)      s = (const float4*)(X1g + j0 * ED) + (k - 160);
            else if (k < 344) s = (const float4*)(D0g + j0 * 3) + (k - 320);
            else if (k < 368) s = (const float4*)(D1g + j0 * 3) + (k - 344);
            else if (k < 376) s = (const float4*)(M0g + j0) + (k - 368);
            else              s = (const float4*)(M1g + j0) + (k - 376);
            cp16(dst + (uint32_t)k * 16u, s);
        }
    }
}

// ---------------------------------------------------------------------------
// Kernel 2: fused message + update for TWO nodes per CTA.  grid = NN/2.
// block = 256 (8 warps), 2-CTA occupancy. Each warp: 4 j per 32-j tile,
// both i-rows. LV/Lc loaded ONCE per j, feeding both matvecs (halves the
// dominant L2/L1 stream). Inner machinery otherwise identical to R15 winner.
// ---------------------------------------------------------------------------
__global__ void __launch_bounds__(256, 2)
main_kernel(const float* __restrict__ scalar, const float* __restrict__ vector,
            const float* __restrict__ expansion, const float* __restrict__ direction,
            const float* __restrict__ mask,
            const float* __restrict__ mRw, const float* __restrict__ mRb,
            const float* __restrict__ uRw1, const float* __restrict__ uRb1,
            const float* __restrict__ uRw2, const float* __restrict__ uRb2,
            const float* __restrict__ Uw, const float* __restrict__ Vw,
            float* __restrict__ out) {
    const int i0 = 2 * blockIdx.x;
    const int i1 = i0 + 1;
    int tid = threadIdx.x;
    int warp = tid >> 5, lane = tid & 31;

    __shared__ __align__(16) float4 smBuf[NSTAGE][TB_F4];   // 24 KB
    __shared__ float red[2][8][4][32];                      // 8 KB
    __shared__ float ds[32], dv[96];
    __shared__ float s_new[32], v_new[96], lu[96], ru[96], feats[64], hbuf[32], og[96];

    // mR_w columns owned by this lane, packed as e-pairs (60 regs).
    ull wA[ED / 2], wB[ED / 2], wC[ED / 2];
#pragma unroll
    for (int q = 0; q < ED / 2; q++) {
        wA[q] = pack2(mRw[(2 * q) * 96 + lane],      mRw[(2 * q + 1) * 96 + lane]);
        wB[q] = pack2(mRw[(2 * q) * 96 + 32 + lane], mRw[(2 * q + 1) * 96 + 32 + lane]);
        wC[q] = pack2(mRw[(2 * q) * 96 + 64 + lane], mRw[(2 * q + 1) * 96 + 64 + lane]);
    }
    const ull biasA = pack2(mRb[lane], 0.f);
    const ull biasB = pack2(mRb[32 + lane], 0.f);
    const ull biasC = pack2(mRb[64 + lane], 0.f);

    const float* X0g = expansion + (size_t)i0 * NN * ED;
    const float* X1g = expansion + (size_t)i1 * NN * ED;
    const float* M0g = mask + (size_t)i0 * NN;
    const float* M1g = mask + (size_t)i1 * NN;
    const float* D0g = direction + (size_t)i0 * NN * 3;
    const float* D1g = direction + (size_t)i1 * NN * 3;

    float a0s = 0.f, a0v0 = 0.f, a0v1 = 0.f, a0v2 = 0.f;
    float a1s = 0.f, a1v0 = 0.f, a1v1 = 0.f, a1v2 = 0.f;

    // prologue: stage tiles 0..2 (3 groups in flight)
    stage_tile(smBuf[0], 0 * JT, tid, X0g, X1g, D0g, D1g, M0g, M1g); CP_COMMIT();
    stage_tile(smBuf[1], 1 * JT, tid, X0g, X1g, D0g, D1g, M0g, M1g); CP_COMMIT();
    stage_tile(smBuf[2], 2 * JT, tid, X0g, X1g, D0g, D1g, M0g, M1g); CP_COMMIT();

    for (int t = 0; t < NT; t++) {
        CP_WAIT2();
        __syncthreads();
        if (t + 3 < NT)
            stage_tile(smBuf[(t + 3) & (NSTAGE - 1)], (t + 3) * JT, tid,
                       X0g, X1g, D0g, D1g, M0g, M1g);
        CP_COMMIT();

        const float4* B  = smBuf[t & (NSTAGE - 1)];
        const float* X0 = (const float*)(B);
        const float* X1 = (const float*)(B + 160);
        const float* D0 = (const float*)(B + 320);
        const float* D1 = (const float*)(B + 344);
        const float* M0 = (const float*)(B + 368);
        const float* M1 = (const float*)(B + 376);

        // ---- 4 j per warp; LV/Lc pipelined, each load feeds BOTH i-rows ----
        const int jb = t * JT + warp * 4;
        float4 LVn = g_lv[jb * 32 + lane];
        float  lcn = g_lc[jb * 32 + lane];

#pragma unroll
        for (int u = 0; u < 4; u++) {
            const int jj = warp * 4 + u;

            float4 LVv = LVn;
            float  lc  = lcn;
            if (u < 3) {
                LVn = g_lv[(jb + u + 1) * 32 + lane];
                lcn = g_lc[(jb + u + 1) * 32 + lane];
            }

            // ---- i0 matvec + epilogue ----
            {
                const ulonglong2* xp = (const ulonglong2*)(X0 + jj * ED);
                ull pa2 = biasA, pb2 = biasB, pc2 = biasC;
#pragma unroll
                for (int q5 = 0; q5 < 5; q5++) {
                    ulonglong2 xx = xp[q5];
                    pa2 = ffma2(xx.x, wA[2 * q5], pa2);
                    pb2 = ffma2(xx.x, wB[2 * q5], pb2);
                    pc2 = ffma2(xx.x, wC[2 * q5], pc2);
                    pa2 = ffma2(xx.y, wA[2 * q5 + 1], pa2);
                    pb2 = ffma2(xx.y, wB[2 * q5 + 1], pb2);
                    pc2 = ffma2(xx.y, wC[2 * q5 + 1], pc2);
                }
                float ra = f2lo(pa2) + f2hi(pa2);
                float rb = f2lo(pb2) + f2hi(pb2);
                float rc = f2lo(pc2) + f2hi(pc2);
                float m  = M0[jj];
                float ta = m * ra;
                a0v0 = fmaf(ta, LVv.x, a0v0);
                a0v1 = fmaf(ta, LVv.y, a0v1);
                a0v2 = fmaf(ta, LVv.z, a0v2);
                a0s  = fmaf(m * rb, LVv.w, a0s);
                float tc = (m * rc) * lc;
                a0v0 = fmaf(tc, D0[jj * 3],     a0v0);
                a0v1 = fmaf(tc, D0[jj * 3 + 1], a0v1);
                a0v2 = fmaf(tc, D0[jj * 3 + 2], a0v2);
            }
            // ---- i1 matvec + epilogue (same LV/Lc) ----
            {
                const ulonglong2* xp = (const ulonglong2*)(X1 + jj * ED);
                ull pa2 = biasA, pb2 = biasB, pc2 = biasC;
#pragma unroll
                for (int q5 = 0; q5 < 5; q5++) {
                    ulonglong2 xx = xp[q5];
                    pa2 = ffma2(xx.x, wA[2 * q5], pa2);
                    pb2 = ffma2(xx.x, wB[2 * q5], pb2);
                    pc2 = ffma2(xx.x, wC[2 * q5], pc2);
                    pa2 = ffma2(xx.y, wA[2 * q5 + 1], pa2);
                    pb2 = ffma2(xx.y, wB[2 * q5 + 1], pb2);
                    pc2 = ffma2(xx.y, wC[2 * q5 + 1], pc2);
                }
                float ra = f2lo(pa2) + f2hi(pa2);
                float rb = f2lo(pb2) + f2hi(pb2);
                float rc = f2lo(pc2) + f2hi(pc2);
                float m  = M1[jj];
                float ta = m * ra;
                a1v0 = fmaf(ta, LVv.x, a1v0);
                a1v1 = fmaf(ta, LVv.y, a1v1);
                a1v2 = fmaf(ta, LVv.z, a1v2);
                a1s  = fmaf(m * rb, LVv.w, a1s);
                float tc = (m * rc) * lc;
                a1v0 = fmaf(tc, D1[jj * 3],     a1v0);
                a1v1 = fmaf(tc, D1[jj * 3 + 1], a1v1);
                a1v2 = fmaf(tc, D1[jj * 3 + 2], a1v2);
            }
        }
    }

    // cross-warp reduction (both i)
    red[0][warp][0][lane] = a0s;
    red[0][warp][1][lane] = a0v0;
    red[0][warp][2][lane] = a0v1;
    red[0][warp][3][lane] = a0v2;
    red[1][warp][0][lane] = a1s;
    red[1][warp][1][lane] = a1v0;
    red[1][warp][2][lane] = a1v1;
    red[1][warp][3][lane] = a1v2;

    // ---- update phase, once per i (verified epilogue, looped) ----
#pragma unroll 1
    for (int ii = 0; ii < 2; ii++) {
        const int i = i0 + ii;
        __syncthreads();
        if (tid < 128) {
            int a = tid >> 5, f = tid & 31;
            float s = 0.f;
#pragma unroll
            for (int w = 0; w < 8; w++) s += red[ii][w][a][f];
            if (a == 0) ds[f] = s; else dv[(a - 1) * 32 + f] = s;
        }
        __syncthreads();

        if (tid < 32) s_new[tid] = scalar[i * 32 + tid] + ds[tid];
        if (tid < 96) v_new[tid] = vector[i * 96 + tid] + dv[tid];
        __syncthreads();

        if (tid < 96) {  // left = v_new @ U_w, right = v_new @ V_w
            int d = tid >> 5, f = tid & 31;
            float a1 = 0.f, a2 = 0.f;
#pragma unroll
            for (int k = 0; k < 32; k++) {
                float v = v_new[d * 32 + k];
                a1 += v * Uw[k * 32 + f];
                a2 += v * Vw[k * 32 + f];
            }
            lu[tid] = a1;
            ru[tid] = a2;
        }
        __syncthreads();
        if (tid < 32) {
            float r0 = ru[tid], r1 = ru[32 + tid], r2 = ru[64 + tid];
            feats[tid] = s_new[tid];
            feats[32 + tid] = sqrtf(r0 * r0 + r1 * r1 + r2 * r2);
        }
        __syncthreads();
        if (tid < 32) {
            float acc = uRb1[tid];
#pragma unroll
            for (int k = 0; k < 64; k++) acc += feats[k] * uRw1[k * 32 + tid];
            hbuf[tid] = acc / (1.0f + expf(-acc));   // silu
        }
        __syncthreads();
        if (tid < 96) {
            float acc = uRb2[tid];
#pragma unroll
            for (int k = 0; k < 32; k++) acc += hbuf[k] * uRw2[k * 96 + tid];
            og[tid] = acc;
        }
        __syncthreads();
        if (tid < 32) {  // scalar out: s_new + inner*b + c
            float inner = lu[tid] * ru[tid] + lu[32 + tid] * ru[32 + tid]
                        + lu[64 + tid] * ru[64 + tid];
            out[i * 32 + tid] = s_new[tid] + inner * og[32 + tid] + og[64 + tid];
        }
        if (tid < 96) {  // vector out: v_new + a*left
            out[NN * 32 + i * 96 + tid] = v_new[tid] + og[tid & 31] * lu[tid];
        }
    }
}

// ---------------------------------------------------------------------------
// launch
// inputs (metadata order): 0 scalar, 1 vector, 2 expansion, 3 direction, 4 mask,
// 5 mL_w1, 6 mL_b1, 7 mL_w2, 8 mL_b2, 9 mR_w, 10 mR_b,
// 11 uR_w1, 12 uR_b1, 13 uR_w2, 14 uR_b2, 15 U_w, 16 V_w
// output: [scalar_out (1024*32) | vector_out (1024*96)] fp32
// ---------------------------------------------------------------------------
extern "C" void kernel_launch(void* const* d_in, const int* in_sizes, int n_in,
                              void* d_out, int out_size) {
    const float* scalar    = (const float*)d_in[0];
    const float* vector    = (const float*)d_in[1];
    const float* expansion = (const float*)d_in[2];
    const float* direction = (const float*)d_in[3];
    const float* mask      = (const float*)d_in[4];
    const float* mL_w1 = (const float*)d_in[5];
    const float* mL_b1 = (const float*)d_in[6];
    const float* mL_w2 = (const float*)d_in[7];
    const float* mL_b2 = (const float*)d_in[8];
    const float* mR_w  = (const float*)d_in[9];
    const float* mR_b  = (const float*)d_in[10];
    const float* uR_w1 = (const float*)d_in[11];
    const float* uR_b1 = (const float*)d_in[12];
    const float* uR_w2 = (const float*)d_in[13];
    const float* uR_b2 = (const float*)d_in[14];
    const float* U_w   = (const float*)d_in[15];
    const float* V_w   = (const float*)d_in[16];
    float* out = (float*)d_out;

    left_kernel<<<NN, 96>>>(scalar, vector, mL_w1, mL_b1, mL_w2, mL_b2);
    main_kernel<<<NN / 2, 256>>>(scalar, vector, expansion, direction, mask,
                                 mR_w, mR_b, uR_w1, uR_b1, uR_w2, uR_b2,
                                 U_w, V_w, out);
}